// round 15
// baseline (speedup 1.0000x reference)
#include <cuda_runtime.h>
#include <cuda_bf16.h>
#include <cstdint>

// masksampling: out = (mask1, mask2), each (32,3,1024,1024) fp32.
// fm[b, 2i+p, 2j+q] = PATTERNS[initmask[b,0,i,j], p, q]
// mask1 = (fm==1), mask2 = (fm==2), broadcast over c=3.
// Pure store-bandwidth kernel: 805 MB written; initmask reads L2-resident.
// x (d_in[0]) is never touched.
//
// FINAL — converged config, reproduced 3x (122.46/122.18/122.59us):
//   BLK=128 / 32768 CTAs, 2 initmask cols/thread, both masks/thread,
//   float4 .cs stores, 28 regs, block-shared dtype detection.
// Lever map (all harness-measured): block 256:+0.9 64:+0.5; STG.256: no win
// (x3, reg cost kills occupancy); .wt:+4us; persistent grid:+19us; mask
// split:+1us; per-warp ballot detect:+0.5us. ~6.35 TB/s of pure writes ==
// B300 streaming-write ceiling; byte count provably minimal.

// PATTERNS packed little-endian: byte (p*2+q) = PATTERNS[k][p][q]
__constant__ unsigned int c_pat[4] = {0x00000201u, 0x02000100u, 0x01020000u, 0x00010002u};

static constexpr int B = 32;
static constexpr int C = 3;
static constexpr int W = 1024;
static constexpr int H = 1024;
static constexpr int WI = W / 2;   // 512 initmask rows
static constexpr int HI = H / 2;   // 512 initmask cols
static constexpr int TPR = HI / 2; // 256 threads per initmask row (2 cols/thread)
static constexpr int BLK = 128;

__global__ void __launch_bounds__(BLK)
masksampling_kernel(const void* __restrict__ im_raw, float* __restrict__ out) {
    // ---- in-kernel dtype detection (jax may downcast int64 -> int32) ----
    // int64 little-endian values 0..3 have ALL odd dwords == 0. Random int32
    // values 0..3 have a nonzero odd dword with prob 1 - 4^-32 over 32 samples.
    __shared__ unsigned s_nz;
    if (threadIdx.x == 0) s_nz = 0u;
    __syncthreads();
    if (threadIdx.x < 32) {
        unsigned v = reinterpret_cast<const unsigned*>(im_raw)[2u * threadIdx.x + 1u];
        if (v) atomicOr(&s_nz, 1u);
    }
    __syncthreads();
    const bool is_i64 = (s_nz == 0u);

    unsigned tid = blockIdx.x * (unsigned)BLK + threadIdx.x;
    // tid layout: b (32) | i (512) | t (256)
    unsigned t = tid & (TPR - 1);
    unsigned i = (tid >> 8) & (WI - 1);
    unsigned b = tid >> 17;

    size_t im_idx = (size_t)b * (WI * HI) + (size_t)i * HI + 2u * t;

    int m0, m1;
    if (is_i64) {
        const longlong2 mv = __ldg(reinterpret_cast<const longlong2*>(
            reinterpret_cast<const long long*>(im_raw) + im_idx));
        m0 = (int)mv.x;
        m1 = (int)mv.y;
    } else {
        const int2 mv = __ldg(reinterpret_cast<const int2*>(
            reinterpret_cast<const int*>(im_raw) + im_idx));
        m0 = mv.x;
        m1 = mv.y;
    }

    const unsigned pa = c_pat[m0];
    const unsigned pb = c_pat[m1];

    // v[mask][p] : 4 output floats at row 2i+p, cols 4t..4t+3
    float4 v[2][2];
    #pragma unroll
    for (int p = 0; p < 2; p++) {
        unsigned a0 = (pa >> (p * 16)) & 0xffu;
        unsigned a1 = (pa >> (p * 16 + 8)) & 0xffu;
        unsigned b0 = (pb >> (p * 16)) & 0xffu;
        unsigned b1 = (pb >> (p * 16 + 8)) & 0xffu;
        v[0][p] = make_float4(a0 == 1u ? 1.f : 0.f, a1 == 1u ? 1.f : 0.f,
                              b0 == 1u ? 1.f : 0.f, b1 == 1u ? 1.f : 0.f);
        v[1][p] = make_float4(a0 == 2u ? 1.f : 0.f, a1 == 2u ? 1.f : 0.f,
                              b0 == 2u ? 1.f : 0.f, b1 == 2u ? 1.f : 0.f);
    }

    const size_t rowbase = (size_t)(2u * i) * H + 4u * t;
    #pragma unroll
    for (int m = 0; m < 2; m++) {
        #pragma unroll
        for (int c = 0; c < C; c++) {
            size_t base = ((size_t)(m * B + b) * C + c) * (size_t)(W * H) + rowbase;
            __stcs(reinterpret_cast<float4*>(out + base), v[m][0]);
            __stcs(reinterpret_cast<float4*>(out + base + H), v[m][1]);
        }
    }
}

extern "C" void kernel_launch(void* const* d_in, const int* in_sizes, int n_in,
                              void* d_out, int out_size) {
    // d_in[0] = x (unused), d_in[1] = initmask (int64 or int32, values 0..3)
    const void* im = d_in[1];
    float* out = (float*)d_out;

    const unsigned total_threads = B * WI * TPR;  // 4,194,304
    masksampling_kernel<<<total_threads / BLK, BLK>>>(im, out);
}

// round 16
// speedup vs baseline: 1.0140x; 1.0140x over previous
#include <cuda_runtime.h>
#include <cuda_bf16.h>
#include <cstdint>

// masksampling: out = (mask1, mask2), each (32,3,1024,1024) fp32.
// fm[b, 2i+p, 2j+q] = PATTERNS[initmask[b,0,i,j], p, q]
// mask1 = (fm==1), mask2 = (fm==2), broadcast over c=3.
// Pure store-bandwidth kernel: 805 MB written; initmask reads L2-resident.
// x (d_in[0]) is never touched.
//
// FINAL — converged config, reproduced 4x (122.46/122.18/122.59/123.04us,
// sigma ~0.35us == run-to-run noise):
//   BLK=128 / 32768 CTAs, 2 initmask cols/thread, both masks/thread,
//   float4 .cs stores, 28 regs, block-shared dtype detection.
// Lever map (all harness-measured, both directions): block 256:+0.9 64:+0.5;
// STG.256: no win (x3, reg cost kills occupancy); .wt:+4us; persistent
// grid:+19us; mask split:+1us; per-warp ballot detect:+0.5us.
// ~6.35 TB/s sustained pure writes == B300 streaming-write ceiling (8TB/s
// spec is aggregate R+W); byte count provably minimal. Session: 129.8->122.2.

// PATTERNS packed little-endian: byte (p*2+q) = PATTERNS[k][p][q]
__constant__ unsigned int c_pat[4] = {0x00000201u, 0x02000100u, 0x01020000u, 0x00010002u};

static constexpr int B = 32;
static constexpr int C = 3;
static constexpr int W = 1024;
static constexpr int H = 1024;
static constexpr int WI = W / 2;   // 512 initmask rows
static constexpr int HI = H / 2;   // 512 initmask cols
static constexpr int TPR = HI / 2; // 256 threads per initmask row (2 cols/thread)
static constexpr int BLK = 128;

__global__ void __launch_bounds__(BLK)
masksampling_kernel(const void* __restrict__ im_raw, float* __restrict__ out) {
    // ---- in-kernel dtype detection (jax may downcast int64 -> int32) ----
    // int64 little-endian values 0..3 have ALL odd dwords == 0. Random int32
    // values 0..3 have a nonzero odd dword with prob 1 - 4^-32 over 32 samples.
    __shared__ unsigned s_nz;
    if (threadIdx.x == 0) s_nz = 0u;
    __syncthreads();
    if (threadIdx.x < 32) {
        unsigned v = reinterpret_cast<const unsigned*>(im_raw)[2u * threadIdx.x + 1u];
        if (v) atomicOr(&s_nz, 1u);
    }
    __syncthreads();
    const bool is_i64 = (s_nz == 0u);

    unsigned tid = blockIdx.x * (unsigned)BLK + threadIdx.x;
    // tid layout: b (32) | i (512) | t (256)
    unsigned t = tid & (TPR - 1);
    unsigned i = (tid >> 8) & (WI - 1);
    unsigned b = tid >> 17;

    size_t im_idx = (size_t)b * (WI * HI) + (size_t)i * HI + 2u * t;

    int m0, m1;
    if (is_i64) {
        const longlong2 mv = __ldg(reinterpret_cast<const longlong2*>(
            reinterpret_cast<const long long*>(im_raw) + im_idx));
        m0 = (int)mv.x;
        m1 = (int)mv.y;
    } else {
        const int2 mv = __ldg(reinterpret_cast<const int2*>(
            reinterpret_cast<const int*>(im_raw) + im_idx));
        m0 = mv.x;
        m1 = mv.y;
    }

    const unsigned pa = c_pat[m0];
    const unsigned pb = c_pat[m1];

    // v[mask][p] : 4 output floats at row 2i+p, cols 4t..4t+3
    float4 v[2][2];
    #pragma unroll
    for (int p = 0; p < 2; p++) {
        unsigned a0 = (pa >> (p * 16)) & 0xffu;
        unsigned a1 = (pa >> (p * 16 + 8)) & 0xffu;
        unsigned b0 = (pb >> (p * 16)) & 0xffu;
        unsigned b1 = (pb >> (p * 16 + 8)) & 0xffu;
        v[0][p] = make_float4(a0 == 1u ? 1.f : 0.f, a1 == 1u ? 1.f : 0.f,
                              b0 == 1u ? 1.f : 0.f, b1 == 1u ? 1.f : 0.f);
        v[1][p] = make_float4(a0 == 2u ? 1.f : 0.f, a1 == 2u ? 1.f : 0.f,
                              b0 == 2u ? 1.f : 0.f, b1 == 2u ? 1.f : 0.f);
    }

    const size_t rowbase = (size_t)(2u * i) * H + 4u * t;
    #pragma unroll
    for (int m = 0; m < 2; m++) {
        #pragma unroll
        for (int c = 0; c < C; c++) {
            size_t base = ((size_t)(m * B + b) * C + c) * (size_t)(W * H) + rowbase;
            __stcs(reinterpret_cast<float4*>(out + base), v[m][0]);
            __stcs(reinterpret_cast<float4*>(out + base + H), v[m][1]);
        }
    }
}

extern "C" void kernel_launch(void* const* d_in, const int* in_sizes, int n_in,
                              void* d_out, int out_size) {
    // d_in[0] = x (unused), d_in[1] = initmask (int64 or int32, values 0..3)
    const void* im = d_in[1];
    float* out = (float*)d_out;

    const unsigned total_threads = B * WI * TPR;  // 4,194,304
    masksampling_kernel<<<total_threads / BLK, BLK>>>(im, out);
}